// round 1
// baseline (speedup 1.0000x reference)
#include <cuda_runtime.h>
#include <math.h>
#include <stdint.h>

// ---------------- problem constants ----------------
#define BQ 16
#define NQ 2048
#define DQ 64
#define SQ 512          // NPOINT
#define NSQ 32          // NSAMPLE
#define SCQ 67          // D+3
#define INCH 134        // 2*D+6
#define C0Q 128
#define C1Q 128
#define C2Q 256
#define KSQ (NSQ*SQ)    // 16384
#define JQ (3+DQ+NSQ*DQ+NSQ*3)  // 2211
#define OFF_X 0
#define OFF_P 3
#define OFF_GP 67
#define OFF_GX 2115
#define XYZ_OUT (BQ*3*SQ)            // 24576
#define NP_OUT  ((size_t)BQ*C2Q*SQ)  // 2097152

// ---------------- scratch (device globals; no allocations) ----------------
__device__ float g_agg[(size_t)BQ*SCQ*NQ];
__device__ float g_h1 [(size_t)BQ*SCQ*NQ];
__device__ float g_h2 [(size_t)BQ*SQ*NQ];      // becomes `select` in place
__device__ float g_selT[(size_t)BQ*NQ*SQ];
__device__ float g_inner[(size_t)BQ*SQ*SQ];
__device__ float g_norm[BQ*SQ];
__device__ int   g_amax[SQ];
__device__ int   g_idx[(size_t)BQ*NQ*NSQ];
__device__ float g_ptst[(size_t)BQ*NQ*DQ];
__device__ float g_xyzt[(size_t)BQ*NQ*3];
__device__ float g_Bmat[(size_t)BQ*NQ*JQ];
__device__ float g_Cbig[(size_t)BQ*SQ*JQ];
__device__ float g_E  [(size_t)BQ*INCH*KSQ];
__device__ float g_O0 [(size_t)BQ*C0Q*KSQ];
__device__ float g_O1 [(size_t)BQ*C1Q*KSQ];
__device__ float g_O2 [(size_t)BQ*C2Q*KSQ];
__device__ float g_s1[SCQ],  g_sh1[SCQ];
__device__ float g_s2[SQ],   g_sh2[SQ];
__device__ float g_sc0[C0Q], g_sf0[C0Q];
__device__ float g_sc1[C1Q], g_sf1[C1Q];
__device__ float g_sc2[C2Q], g_sf2[C2Q];
__device__ float g_acc[BQ];
__device__ int   g_flags[NQ];

// ---------------- generic SGEMM: C[b] = A[b](MxK) * B[b](KxN) (+bias, B-affine+leaky) ----
__global__ void __launch_bounds__(256) sa_gemm(
    const float* __restrict__ A, const float* __restrict__ Bm, float* __restrict__ C,
    int M, int Ncol, int K,
    size_t sAb, size_t sBb, size_t sCb,
    const float* __restrict__ bias,
    const float* __restrict__ bsc, const float* __restrict__ bsh)
{
    __shared__ float As[8][128];
    __shared__ float Bs[8][128];
    const int b = blockIdx.z;
    const float* Ab = A + (size_t)b * sAb;
    const float* Bb = Bm + (size_t)b * sBb;
    float* Cb = C + (size_t)b * sCb;
    const int tid = threadIdx.x;
    const int row0 = blockIdx.y * 128;
    const int col0 = blockIdx.x * 128;
    const int ra = (tid >> 4) * 4;
    const int ca = (tid & 15) * 4;
    float acc[8][8];
#pragma unroll
    for (int i = 0; i < 8; i++)
#pragma unroll
        for (int j = 0; j < 8; j++) acc[i][j] = 0.f;

    const int la_m = tid >> 1;
    const int la_k = (tid & 1) * 4;
    const int lb_k = tid >> 5;
    const int lb_n = (tid & 31) * 4;

    for (int k0 = 0; k0 < K; k0 += 8) {
        {
            int arow = row0 + la_m;
#pragma unroll
            for (int u = 0; u < 4; u++) {
                int kk = k0 + la_k + u;
                float v = (arow < M && kk < K) ? Ab[(size_t)arow * K + kk] : 0.f;
                As[la_k + u][la_m] = v;
            }
        }
        {
            int krow = k0 + lb_k;
            bool kv = krow < K;
            float sc = 1.f, sh = 0.f;
            if (bsc && kv) { sc = bsc[krow]; sh = bsh[krow]; }
#pragma unroll
            for (int u = 0; u < 4; u++) {
                int col = col0 + lb_n + u;
                float v = 0.f;
                if (kv && col < Ncol) {
                    v = Bb[(size_t)krow * Ncol + col];
                    if (bsc) { float y = sc * v + sh; v = (y >= 0.f) ? y : 0.2f * y; }
                }
                Bs[lb_k][lb_n + u] = v;
            }
        }
        __syncthreads();
#pragma unroll
        for (int kk = 0; kk < 8; kk++) {
            float4 a0 = *(const float4*)&As[kk][ra];
            float4 a1 = *(const float4*)&As[kk][64 + ra];
            float4 b0 = *(const float4*)&Bs[kk][ca];
            float4 b1 = *(const float4*)&Bs[kk][64 + ca];
            float av[8] = {a0.x,a0.y,a0.z,a0.w,a1.x,a1.y,a1.z,a1.w};
            float bv[8] = {b0.x,b0.y,b0.z,b0.w,b1.x,b1.y,b1.z,b1.w};
#pragma unroll
            for (int i = 0; i < 8; i++)
#pragma unroll
                for (int j = 0; j < 8; j++)
                    acc[i][j] += av[i] * bv[j];
        }
        __syncthreads();
    }
#pragma unroll
    for (int i = 0; i < 8; i++) {
        int r = row0 + ((i < 4) ? (ra + i) : (64 + ra + i - 4));
        if (r >= M) continue;
        float bi = bias ? bias[r] : 0.f;
#pragma unroll
        for (int j = 0; j < 8; j++) {
            int c = col0 + ((j < 4) ? (ca + j) : (64 + ca + j - 4));
            if (c < Ncol) Cb[(size_t)r * Ncol + c] = acc[i][j] + bi;
        }
    }
}

// ---------------- small helpers ----------------
__global__ void sa_init() {
    int i = blockIdx.x * 256 + threadIdx.x;
    if (i < NQ) g_flags[i] = 0;
    if (i < BQ) g_acc[i] = 0.f;
}

__global__ void sa_agg(const float* __restrict__ points, const float* __restrict__ xyz) {
    size_t i = (size_t)blockIdx.x * 256 + threadIdx.x;
    if (i >= (size_t)BQ*SCQ*NQ) return;
    int n = (int)(i % NQ); size_t r = i / NQ; int c = (int)(r % SCQ); int b = (int)(r / SCQ);
    float v = (c < DQ) ? points[((size_t)b*DQ + c)*NQ + n]
                       : xyz[((size_t)b*3 + (c - DQ))*NQ + n];
    g_agg[i] = v;
}

// (B,C,N) -> (B,N,C)
__global__ void sa_tr(const float* __restrict__ src, float* __restrict__ dst, int C) {
    size_t i = (size_t)blockIdx.x * 256 + threadIdx.x;
    if (i >= (size_t)BQ * NQ * C) return;
    int c = (int)(i % C); size_t r = i / C; int n = (int)(r % NQ); int b = (int)(r / NQ);
    dst[i] = src[((size_t)b * C + c) * NQ + n];
}

// ball query: warp per (b,n), ordered first-32 under radius
__global__ void sa_ball(const float* __restrict__ xyz) {
    int w = (blockIdx.x * blockDim.x + threadIdx.x) >> 5;
    int lane = threadIdx.x & 31;
    if (w >= BQ * NQ) return;
    int b = w / NQ, n = w % NQ;
    const float* X = xyz + (size_t)b * 3 * NQ;
    float px = X[n], py = X[NQ + n], pz = X[2 * NQ + n];
    float pn = px*px + py*py + pz*pz;
    const float RR = (float)(0.2 * 0.2);
    int* out = g_idx + ((size_t)b * NQ + n) * NSQ;
    int cnt = 0;
    for (int j0 = 0; j0 < NQ && cnt < NSQ; j0 += 32) {
        int j = j0 + lane;
        float qx = X[j], qy = X[NQ + j], qz = X[2 * NQ + j];
        float qn = qx*qx + qy*qy + qz*qz;
        float sq = (pn + qn) - 2.0f * (px*qx + py*qy + pz*qz);
        bool in = !(sq > RR);
        unsigned m = __ballot_sync(0xffffffffu, in);
        int pos = cnt + __popc(m & ((1u << lane) - 1u));
        if (in && pos < NSQ) out[pos] = j;
        cnt += __popc(m);
    }
    __syncwarp();
    if (lane == 0) {
        int first = out[0];
        for (int t = cnt; t < NSQ; t++) out[t] = first;
    }
}

// per-channel BN stats over (B, L): scale/shift
__global__ void sa_stats(const float* __restrict__ X, int Cch, int L,
                         const float* __restrict__ gamma, const float* __restrict__ beta,
                         float* __restrict__ sc, float* __restrict__ sf)
{
    int c = blockIdx.x;
    int tid = threadIdx.x;
    double s = 0.0, s2 = 0.0;
    for (int b = 0; b < BQ; b++) {
        const float* p = X + ((size_t)b * Cch + c) * L;
        for (int i = tid; i < L; i += 256) { double v = p[i]; s += v; s2 += v * v; }
    }
    __shared__ double ss[256], ss2[256];
    ss[tid] = s; ss2[tid] = s2; __syncthreads();
    for (int o = 128; o > 0; o >>= 1) {
        if (tid < o) { ss[tid] += ss[tid + o]; ss2[tid] += ss2[tid + o]; }
        __syncthreads();
    }
    if (tid == 0) {
        double n = (double)BQ * L;
        double m = ss[0] / n;
        double var = ss2[0] / n - m * m;
        if (var < 0.0) var = 0.0;
        float scale = gamma[c] * rsqrtf((float)var + 1e-5f);
        sc[c] = scale;
        sf[c] = beta[c] - (float)m * scale;
    }
}

__global__ void sa_bnapply(float* __restrict__ X, const float* __restrict__ sc,
                           const float* __restrict__ sf, int Cch, int L) {
    size_t i = (size_t)blockIdx.x * 256 + threadIdx.x;
    if (i >= (size_t)BQ * Cch * L) return;
    int c = (int)((i / L) % Cch);
    X[i] = sc[c] * X[i] + sf[c];
}

// softmax over N per (b,s) row, in place; also norm + argmax(b==0)
__global__ void sa_softmax(float* __restrict__ H) {
    int s = blockIdx.x, b = blockIdx.y;
    float* row = H + ((size_t)b * SQ + s) * NQ;
    __shared__ float buf[NQ];
    __shared__ float red[256];
    __shared__ float rv[256];
    __shared__ int   ri[256];
    int tid = threadIdx.x;
    float a = g_s2[s], sh = g_sh2[s];
    float lmax = -3.4e38f;
    for (int i = tid; i < NQ; i += 256) {
        float y = a * row[i] + sh;
        buf[i] = y;
        lmax = fmaxf(lmax, y);
    }
    red[tid] = lmax; __syncthreads();
    for (int o = 128; o > 0; o >>= 1) { if (tid < o) red[tid] = fmaxf(red[tid], red[tid + o]); __syncthreads(); }
    float gmax = red[0]; __syncthreads();
    float lsum = 0.f;
    for (int i = tid; i < NQ; i += 256) { float e = expf(buf[i] - gmax); buf[i] = e; lsum += e; }
    red[tid] = lsum; __syncthreads();
    for (int o = 128; o > 0; o >>= 1) { if (tid < o) red[tid] += red[tid + o]; __syncthreads(); }
    float inv = 1.f / red[0]; __syncthreads();
    float lss = 0.f, bm = -1.f; int bi = 0;
    for (int i = tid; i < NQ; i += 256) {
        float v = buf[i] * inv;
        row[i] = v;
        lss += v * v;
        if (v > bm) { bm = v; bi = i; }
    }
    red[tid] = lss; rv[tid] = bm; ri[tid] = bi; __syncthreads();
    for (int o = 128; o > 0; o >>= 1) {
        if (tid < o) {
            red[tid] += red[tid + o];
            if (rv[tid + o] > rv[tid] || (rv[tid + o] == rv[tid] && ri[tid + o] < ri[tid])) {
                rv[tid] = rv[tid + o]; ri[tid] = ri[tid + o];
            }
        }
        __syncthreads();
    }
    if (tid == 0) {
        g_norm[b * SQ + s] = sqrtf(red[0]);
        if (b == 0) g_amax[s] = ri[0];
    }
}

__global__ void sa_flags() {
    int s = blockIdx.x * 256 + threadIdx.x;
    if (s < SQ) g_flags[g_amax[s]] = 1;
}

// select (b,s,n) -> selT (b,n,s)
__global__ void sa_selT() {
    __shared__ float t[32][33];
    int b = blockIdx.z;
    int n0 = blockIdx.x * 32, s0 = blockIdx.y * 32;
    const float* Sb = g_h2 + (size_t)b * SQ * NQ;
    float* Tb = g_selT + (size_t)b * NQ * SQ;
    int x = threadIdx.x, y = threadIdx.y;
    for (int yy = y; yy < 32; yy += 8)
        t[yy][x] = Sb[(size_t)(s0 + yy) * NQ + (n0 + x)];
    __syncthreads();
    for (int yy = y; yy < 32; yy += 8)
        Tb[(size_t)(n0 + yy) * SQ + (s0 + x)] = t[x][yy];
}

__global__ void sa_cos_epi() {
    size_t i = (size_t)blockIdx.x * 256 + threadIdx.x;
    int b = (int)(i / ((size_t)SQ * SQ));
    int r = (int)((i / SQ) % SQ);
    int c = (int)(i % SQ);
    float v = 0.f;
    if (r != c) {
        float in = g_inner[i];
        float d = g_norm[b * SQ + r] * g_norm[b * SQ + c] + 1e-10f;
        float cm = in / d;
        v = cm * cm;
    }
    __shared__ float red[256];
    red[threadIdx.x] = v; __syncthreads();
    for (int o = 128; o > 0; o >>= 1) { if (threadIdx.x < o) red[threadIdx.x] += red[threadIdx.x + o]; __syncthreads(); }
    if (threadIdx.x == 0) atomicAdd(&g_acc[b], red[0]);
}

// build (n x 2211) gather matrix per (b,n)
__global__ void sa_bmat() {
    int n = blockIdx.x, b = blockIdx.y;
    float* row = g_Bmat + ((size_t)b * NQ + n) * JQ;
    const float* xt = g_xyzt + (size_t)b * NQ * 3;
    const float* pt = g_ptst + (size_t)b * NQ * DQ;
    __shared__ int sidx[NSQ];
    int tid = threadIdx.x;
    if (tid < NSQ) sidx[tid] = g_idx[((size_t)b * NQ + n) * NSQ + tid];
    __syncthreads();
    if (tid < 3) row[OFF_X + tid] = xt[(size_t)n * 3 + tid];
    for (int d = tid; d < DQ; d += 256) row[OFF_P + d] = pt[(size_t)n * DQ + d];
    for (int t = tid; t < NSQ * DQ; t += 256) {
        int k = t / DQ, d = t % DQ;
        row[OFF_GP + t] = pt[(size_t)sidx[k] * DQ + d];
    }
    for (int t = tid; t < NSQ * 3; t += 256) {
        int k = t / 3, c = t % 3;
        row[OFF_GX + t] = xt[(size_t)sidx[k] * 3 + c];
    }
}

__global__ void sa_newxyz(float* __restrict__ out) {
    int i = blockIdx.x * 256 + threadIdx.x;
    if (i >= BQ * 3 * SQ) return;
    int s = i % SQ; int c = (i / SQ) % 3; int b = i / (3 * SQ);
    out[i] = g_Cbig[((size_t)b * SQ + s) * JQ + c];
}

__global__ void sa_edge() {
    size_t i = (size_t)blockIdx.x * 256 + threadIdx.x;
    if (i >= (size_t)BQ * INCH * KSQ) return;
    int s = (int)(i % SQ); size_t r = i / SQ;
    int k = (int)(r % NSQ); r /= NSQ;
    int ch = (int)(r % INCH); int b = (int)(r / INCH);
    const float* Crow = g_Cbig + ((size_t)b * SQ + s) * JQ;
    float v;
    if (ch < 64) v = Crow[OFF_P + ch];
    else if (ch < 128) { int d = ch - 64; v = Crow[OFF_GP + k * DQ + d] - Crow[OFF_P + d]; }
    else if (ch < 131) v = Crow[OFF_X + (ch - 128)];
    else { int c3 = ch - 131; v = Crow[OFF_GX + k * 3 + c3] - Crow[OFF_X + c3]; }
    g_E[i] = v;
}

__global__ void sa_max(float* __restrict__ out) {
    size_t i = (size_t)blockIdx.x * 256 + threadIdx.x;
    if (i >= NP_OUT) return;
    int s = (int)(i % SQ); int o = (int)((i / SQ) % C2Q); int b = (int)(i / ((size_t)SQ * C2Q));
    float sc = g_sc2[o], sf = g_sf2[o];
    const float* p = g_O2 + ((size_t)b * C2Q + o) * KSQ + s;
    float m = -3.4e38f;
#pragma unroll
    for (int k = 0; k < NSQ; k++) {
        float x = p[(size_t)k * SQ];
        float y = sc * x + sf;
        y = (y >= 0.f) ? y : 0.2f * y;
        m = fmaxf(m, y);
    }
    out[XYZ_OUT + i] = m;
}

__global__ void sa_scalars(float* __restrict__ out) {
    __shared__ float sfr[256];
    __shared__ int sir[256];
    int tid = threadIdx.x;
    int cnt = 0;
    for (int i = tid; i < NQ; i += 256) cnt += g_flags[i];
    float l = (tid < BQ) ? sqrtf(g_acc[tid]) : 0.f;
    sfr[tid] = l; sir[tid] = cnt; __syncthreads();
    for (int o = 128; o > 0; o >>= 1) {
        if (tid < o) { sfr[tid] += sfr[tid + o]; sir[tid] += sir[tid + o]; }
        __syncthreads();
    }
    if (tid == 0) {
        out[XYZ_OUT + NP_OUT]     = sfr[0] / (float)BQ;
        out[XYZ_OUT + NP_OUT + 1] = (float)sir[0];
    }
}

// ---------------- launch ----------------
static inline float* symf(const void* sym) { void* p = nullptr; cudaGetSymbolAddress(&p, sym); return (float*)p; }

extern "C" void kernel_launch(void* const* d_in, const int* in_sizes, int n_in,
                              void* d_out, int out_size)
{
    const float* xyz    = (const float*)d_in[0];
    const float* points = (const float*)d_in[1];
    const float* w1_w = (const float*)d_in[2];
    const float* w1_b = (const float*)d_in[3];
    const float* bn1g = (const float*)d_in[4];
    const float* bn1b = (const float*)d_in[5];
    const float* w2_w = (const float*)d_in[6];
    const float* w2_b = (const float*)d_in[7];
    const float* bn2g = (const float*)d_in[8];
    const float* bn2b = (const float*)d_in[9];
    const float* c0w = (const float*)d_in[10];
    const float* c0b = (const float*)d_in[11];
    const float* g0  = (const float*)d_in[12];
    const float* b0  = (const float*)d_in[13];
    const float* c1w = (const float*)d_in[14];
    const float* c1b = (const float*)d_in[15];
    const float* g1  = (const float*)d_in[16];
    const float* b1  = (const float*)d_in[17];
    const float* c2w = (const float*)d_in[18];
    const float* c2b = (const float*)d_in[19];
    const float* g2  = (const float*)d_in[20];
    const float* b2  = (const float*)d_in[21];
    float* out = (float*)d_out;

    float* p_agg  = symf(g_agg);
    float* p_h1   = symf(g_h1);
    float* p_h2   = symf(g_h2);
    float* p_selT = symf(g_selT);
    float* p_inner= symf(g_inner);
    float* p_ptst = symf(g_ptst);
    float* p_xyzt = symf(g_xyzt);
    float* p_Bmat = symf(g_Bmat);
    float* p_C    = symf(g_Cbig);
    float* p_E    = symf(g_E);
    float* p_O0   = symf(g_O0);
    float* p_O1   = symf(g_O1);
    float* p_O2   = symf(g_O2);
    float* p_s1   = symf(g_s1);
    float* p_sh1  = symf(g_sh1);
    float* p_s2   = symf(g_s2);
    float* p_sh2  = symf(g_sh2);
    float* p_sc0  = symf(g_sc0);
    float* p_sf0  = symf(g_sf0);
    float* p_sc1  = symf(g_sc1);
    float* p_sf1  = symf(g_sf1);
    float* p_sc2  = symf(g_sc2);
    float* p_sf2  = symf(g_sf2);

    sa_init<<<9, 256>>>();

    // agg = concat(points, xyz) channel-major
    sa_agg<<<(int)(((size_t)BQ*SCQ*NQ + 255) / 256), 256>>>(points, xyz);
    // transposes for gather
    sa_tr<<<(int)(((size_t)BQ*NQ*DQ + 255) / 256), 256>>>(points, p_ptst, DQ);
    sa_tr<<<(int)(((size_t)BQ*NQ*3 + 255) / 256), 256>>>(xyz, p_xyzt, 3);
    // ball query
    sa_ball<<<(BQ * NQ * 32) / 256, 256>>>(xyz);

    // h1 = w1 @ agg + b1
    sa_gemm<<<dim3(16, 1, BQ), 256>>>(w1_w, p_agg, p_h1, SCQ, NQ, SCQ,
                                      0, (size_t)SCQ*NQ, (size_t)SCQ*NQ, w1_b, nullptr, nullptr);
    sa_stats<<<SCQ, 256>>>(p_h1, SCQ, NQ, bn1g, bn1b, p_s1, p_sh1);
    sa_bnapply<<<(int)(((size_t)BQ*SCQ*NQ + 255) / 256), 256>>>(p_h1, p_s1, p_sh1, SCQ, NQ);

    // h2 = w2 @ h1 + b2
    sa_gemm<<<dim3(16, 4, BQ), 256>>>(w2_w, p_h1, p_h2, SQ, NQ, SCQ,
                                      0, (size_t)SCQ*NQ, (size_t)SQ*NQ, w2_b, nullptr, nullptr);
    sa_stats<<<SQ, 256>>>(p_h2, SQ, NQ, bn2g, bn2b, p_s2, p_sh2);
    // softmax(bn2(h2)) in place -> select; also norms + argmax(b=0)
    sa_softmax<<<dim3(SQ, BQ), 256>>>(p_h2);
    sa_flags<<<2, 256>>>();

    // cosine loss: inner = S S^T
    sa_selT<<<dim3(NQ / 32, SQ / 32, BQ), dim3(32, 8)>>>();
    sa_gemm<<<dim3(4, 4, BQ), 256>>>(p_h2, p_selT, p_inner, SQ, SQ, NQ,
                                     (size_t)SQ*NQ, (size_t)NQ*SQ, (size_t)SQ*SQ,
                                     nullptr, nullptr, nullptr);
    sa_cos_epi<<<(int)(((size_t)BQ*SQ*SQ) / 256), 256>>>();

    // grouped feature matrix + big GEMM
    sa_bmat<<<dim3(NQ, BQ), 256>>>();
    sa_gemm<<<dim3((JQ + 127) / 128, 4, BQ), 256>>>(p_h2, p_Bmat, p_C, SQ, JQ, NQ,
                                                    (size_t)SQ*NQ, (size_t)NQ*JQ, (size_t)SQ*JQ,
                                                    nullptr, nullptr, nullptr);
    sa_newxyz<<<(BQ*3*SQ + 255) / 256, 256>>>(out);
    sa_edge<<<(int)(((size_t)BQ*INCH*KSQ + 255) / 256), 256>>>();

    // conv stack
    sa_gemm<<<dim3(KSQ / 128, 1, BQ), 256>>>(c0w, p_E, p_O0, C0Q, KSQ, INCH,
                                             0, (size_t)INCH*KSQ, (size_t)C0Q*KSQ, c0b, nullptr, nullptr);
    sa_stats<<<C0Q, 256>>>(p_O0, C0Q, KSQ, g0, b0, p_sc0, p_sf0);
    sa_gemm<<<dim3(KSQ / 128, 1, BQ), 256>>>(c1w, p_O0, p_O1, C1Q, KSQ, C0Q,
                                             0, (size_t)C0Q*KSQ, (size_t)C1Q*KSQ, c1b, p_sc0, p_sf0);
    sa_stats<<<C1Q, 256>>>(p_O1, C1Q, KSQ, g1, b1, p_sc1, p_sf1);
    sa_gemm<<<dim3(KSQ / 128, 2, BQ), 256>>>(c2w, p_O1, p_O2, C2Q, KSQ, C1Q,
                                             0, (size_t)C1Q*KSQ, (size_t)C2Q*KSQ, c2b, p_sc1, p_sf1);
    sa_stats<<<C2Q, 256>>>(p_O2, C2Q, KSQ, g2, b2, p_sc2, p_sf2);

    // BN+leaky+max over k -> new_points
    sa_max<<<(int)((NP_OUT + 255) / 256), 256>>>(out);
    // scalars
    sa_scalars<<<1, 256>>>(out);
}